// round 11
// baseline (speedup 1.0000x reference)
#include <cuda_runtime.h>
#include <cstdint>

#define BB 64
#define NN 512
#define DD 64
#define HH 4
#define CC 64
#define NEGS 0.2f

typedef unsigned long long ull;

// Scratch (device globals - no runtime allocation allowed)
__device__ float g_x[BB*NN*DD];             // layer activations
__device__ float g_asrc[BB*HH*NN];          // [b][h][n]
__device__ float g_adst[BB*HH*NN];          // [b][h][n]
__device__ float g_S1f[BB*HH*520*CC];       // full suffix sums (x-space)
__device__ float g_P2f[BB*HH*520*CC];       // full prefix sums (x-space)
__device__ float g_r1[BB*HH*NN];            // 0.25*e^{d}/den per i
__device__ float g_r2[BB*HH*NN];            // 0.25*e^{.2d}/den per i
__device__ int   g_k[BB*HH*NN];             // split index per i
__device__ float g_Wr[3*HH*64*64];          // [l][h][k][c] = W_l[(h*64+c)*64+k]
__device__ float g_vsd[3*2*HH*64];          // [l][s/d][h][k] projected att vecs

// ---- f32x2 helpers -------------------------------------------------------
__device__ __forceinline__ ull packdup(float a) {
    ull r; asm("mov.b64 %0, {%1, %1};" : "=l"(r) : "f"(a)); return r;
}
__device__ __forceinline__ void fma2(ull& d, ull a, ull b) {
    asm("fma.rn.f32x2 %0, %1, %2, %0;" : "+l"(d) : "l"(a), "l"(b));
}
__device__ __forceinline__ float2 unpack2(ull v) {
    float2 r; asm("mov.b64 {%0, %1}, %2;" : "=f"(r.x), "=f"(r.y) : "l"(v));
    return r;
}

// ---------------------------------------------------------------------------
// k_wr (once): rearrange lin_w into g_Wr[l][h][k][c]; project attention vecs.
// ---------------------------------------------------------------------------
__global__ __launch_bounds__(256) void k_wr(
    const float* __restrict__ lin,
    const float* __restrict__ attS, const float* __restrict__ attD)
{
    const int l = blockIdx.x >> 2, h = blockIdx.x & 3;
    const float* W = lin + l * 16384;
    float* dst = g_Wr + blockIdx.x * 4096;
    const int t = threadIdx.x;
    const int c = t & 63, qq = t >> 6;
    #pragma unroll
    for (int j4 = 0; j4 < 4; j4++) {
        float4 v = *(const float4*)(W + (h * 64 + c) * 64 + qq * 16 + j4 * 4);
        dst[(qq * 16 + j4 * 4 + 0) * 64 + c] = v.x;
        dst[(qq * 16 + j4 * 4 + 1) * 64 + c] = v.y;
        dst[(qq * 16 + j4 * 4 + 2) * 64 + c] = v.z;
        dst[(qq * 16 + j4 * 4 + 3) * 64 + c] = v.w;
    }
    if (t < 128) {
        const int k = t & 63;
        const float* av = (t < 64) ? (attS + (l * HH + h) * 64)
                                   : (attD + (l * HH + h) * 64);
        float acc = 0.f;
        #pragma unroll 8
        for (int c2 = 0; c2 < 64; c2++)
            acc += av[c2] * W[(h * 64 + c2) * 64 + k];
        g_vsd[((l * 2 + (t >> 6)) * HH + h) * 64 + k] = acc;
    }
}

// ---------------------------------------------------------------------------
// k_att: a_src[n,h] = x[n]·vs[h], a_dst[n,h] = x[n]·vd[h] (vecs precomputed).
// ---------------------------------------------------------------------------
__global__ __launch_bounds__(512) void k_att(
    const float* __restrict__ x, const float* __restrict__ vsd)
{
    __shared__ float s_v[512];
    __shared__ float s_xt[128][68];
    const int t  = threadIdx.x;
    const int b  = blockIdx.x;
    const int n0 = blockIdx.y * 128;

    s_v[t] = vsd[t];
    {
        const int r = t >> 2, q = t & 3;
        const float4* xp = (const float4*)(x + ((size_t)(b * NN + n0 + r)) * 64 + q * 16);
        #pragma unroll
        for (int j4 = 0; j4 < 4; j4++)
            *(float4*)&s_xt[r][q * 16 + j4 * 4] = xp[j4];
    }
    __syncthreads();

    {
        const int n = t >> 2, h = t & 3;
        const float* xr = s_xt[n];
        const float* vs = s_v + h * 64;
        const float* vd = s_v + 256 + h * 64;
        float as = 0.f, ad = 0.f;
        #pragma unroll 8
        for (int c = 0; c < 64; c++) {
            float xv = xr[c];
            as += xv * vs[c];
            ad += xv * vd[c];
        }
        int gi = (b * HH + h) * NN + n0 + n;
        g_asrc[gi] = as;
        g_adst[gi] = ad;
    }
}

// ---------------------------------------------------------------------------
// k_prep, 512 threads, one block per (b,h): sort s; chunk(8) sums+scans in
// x-space; full per-position suffix/prefix arrays to global; per-i r1/r2/k.
// ---------------------------------------------------------------------------
extern __shared__ float psm[];

__global__ __launch_bounds__(512) void k_prep(const float* __restrict__ xin)
{
    float* s_s  = psm;              // 512
    float* s_dd = psm + 512;
    float* s_W1 = psm + 1024;
    float* s_W2 = psm + 1536;
    int*   s_pj = (int*)(psm + 2048);
    float* CH1  = psm + 2560;       // [66][64]
    float* CH2  = psm + 6784;       // [66][64]
    float* CH1d = psm + 11008;      // [66]
    float* CH2d = psm + 11074;      // [66]
    float* s1d  = psm + 11140;      // [520]
    float* p2d  = psm + 11660;      // [520]  -> 12180 floats

    const int t = threadIdx.x;
    const int b = blockIdx.x;
    const int h = blockIdx.y;
    const int bh = b * HH + h;

    s_s[t]  = g_asrc[bh * NN + t];
    s_pj[t] = t;
    s_dd[t] = g_adst[bh * NN + t];

    // bitonic sort ascending; j<=32 stages warp-local
    {
        int prev_cross = 1;
        for (int k = 2; k <= 512; k <<= 1) {
            for (int j = k >> 1; j > 0; j >>= 1) {
                int cross = (j >= 64);
                if (cross | prev_cross) __syncthreads(); else __syncwarp();
                if (t < 256) {
                    int i = ((t & ~(j - 1)) << 1) | (t & (j - 1));
                    int p = i | j;
                    bool up = ((i & k) == 0);
                    float ki = s_s[i], kp = s_s[p];
                    if (up ? (ki > kp) : (ki < kp)) {
                        s_s[i] = kp; s_s[p] = ki;
                        int tmp = s_pj[i]; s_pj[i] = s_pj[p]; s_pj[p] = tmp;
                    }
                }
                prev_cross = cross;
            }
        }
        __syncthreads();
    }

    // sorted weights + per-i split
    int k_reg;
    {
        float sv = s_s[t];
        s_W1[t] = __expf(sv);
        s_W2[t] = __expf(NEGS * sv);
        float thr = -s_dd[t];
        int lo = 0, hi = 512;
        while (lo < hi) {
            int mid = (lo + hi) >> 1;
            if (s_s[mid] < thr) lo = mid + 1; else hi = mid;
        }
        k_reg = lo;
    }
    __syncthreads();

    const float* xb = xin + (size_t)b * NN * 64;

    // chunk sums (float2 over x rows)
    #pragma unroll
    for (int p = t; p < 2048; p += 512) {
        int m = p >> 5, c = (p & 31) * 2;
        float2 f1 = make_float2(0.f, 0.f), f2 = make_float2(0.f, 0.f);
        #pragma unroll
        for (int r = 0; r < 8; r++) {
            int jj = m * 8 + r;
            float2 hv = *(const float2*)(xb + (size_t)s_pj[jj] * 64 + c);
            float w1 = s_W1[jj], w2 = s_W2[jj];
            f1.x += w1 * hv.x; f1.y += w1 * hv.y;
            f2.x += w2 * hv.x; f2.y += w2 * hv.y;
        }
        *(float2*)&CH1[m * 64 + c] = f1;
        *(float2*)&CH2[(m + 1) * 64 + c] = f2;
    }
    if (t < 64) {
        int m = t;
        float f1 = 0.f, f2 = 0.f;
        #pragma unroll
        for (int r = 0; r < 8; r++) { f1 += s_W1[m*8+r]; f2 += s_W2[m*8+r]; }
        CH1d[m] = f1;
        CH2d[m + 1] = f2;
    }
    __syncthreads();

    // chunk scans
    if (t < 64) {
        const int c = t;
        CH1[64 * 64 + c] = 0.f;
        CH2[c] = 0.f;
        float run = 0.f;
        for (int m = 63; m >= 0; m--) { run += CH1[m * 64 + c]; CH1[m * 64 + c] = run; }
        float run2 = 0.f;
        for (int m = 1; m <= 64; m++) { run2 += CH2[m * 64 + c]; CH2[m * 64 + c] = run2; }
    } else if (t == 64) {
        CH1d[64] = 0.f;
        float run = 0.f;
        for (int m = 63; m >= 0; m--) { run += CH1d[m]; CH1d[m] = run; }
    } else if (t == 65) {
        CH2d[0] = 0.f;
        float run = 0.f;
        for (int m = 1; m <= 64; m++) { run += CH2d[m]; CH2d[m] = run; }
    }
    __syncthreads();

    // full per-position arrays + scalar arrays
    {
        float* S1 = g_S1f + (size_t)bh * 520 * 64;
        float* P2 = g_P2f + (size_t)bh * 520 * 64;
        #pragma unroll
        for (int p = t; p < 2048; p += 512) {
            int m = p >> 5, c = (p & 31) * 2;
            float2 hv[8];
            #pragma unroll
            for (int r = 0; r < 8; r++)
                hv[r] = *(const float2*)(xb + (size_t)s_pj[m * 8 + r] * 64 + c);
            float2 run1 = *(const float2*)&CH1[(m + 1) * 64 + c];
            #pragma unroll
            for (int r = 7; r >= 0; r--) {
                float w = s_W1[m * 8 + r];
                run1.x += w * hv[r].x; run1.y += w * hv[r].y;
                *(float2*)&S1[(size_t)(m * 8 + r) * 64 + c] = run1;
            }
            float2 run2 = *(const float2*)&CH2[m * 64 + c];
            #pragma unroll
            for (int r = 0; r < 8; r++) {
                *(float2*)&P2[(size_t)(m * 8 + r) * 64 + c] = run2;
                float w = s_W2[m * 8 + r];
                run2.x += w * hv[r].x; run2.y += w * hv[r].y;
            }
        }
        if (t < 64) {
            int m = t;
            float run1 = CH1d[m + 1];
            #pragma unroll
            for (int r = 7; r >= 0; r--) { run1 += s_W1[m*8+r]; s1d[m*8+r] = run1; }
            float run2 = CH2d[m];
            #pragma unroll
            for (int r = 0; r < 8; r++) { p2d[m*8+r] = run2; run2 += s_W2[m*8+r]; }
        }
        if (t < 64) {
            S1[(size_t)512 * 64 + t] = 0.f;
            P2[(size_t)512 * 64 + t] = CH2[64 * 64 + t];
        }
        if (t == 64) { s1d[512] = 0.f; p2d[512] = CH2d[64]; }
    }
    __syncthreads();

    // per-i scalars
    {
        float dv = s_dd[t];
        float e1 = __expf(dv);
        float e2 = __expf(NEGS * dv);
        float den = e1 * s1d[k_reg] + e2 * p2d[k_reg];
        float inv = 0.25f * __frcp_rn(den);
        int gi = bh * NN + t;
        g_r1[gi] = e1 * inv;
        g_r2[gi] = e2 * inv;
        g_k[gi]  = k_reg;
    }
}

// ---------------------------------------------------------------------------
// k_emit (v3): 32-i tiles, grid (64 b, 16) = 1024 blocks, 256 threads,
// ~28KB smem, __launch_bounds__(256,6) -> ~6 blocks/SM (~48 warps).
// Per head h: formation (float4-coalesced rows of S1f/P2f -> Ux[i][k]),
// stage Wr[h] chunk, 64-k f32x2 GEMM (1i x 8c). Epilogue: bias+relu -> g_x.
// ---------------------------------------------------------------------------
__global__ __launch_bounds__(256, 6) void k_emit(
    const float* __restrict__ cb, const float* __restrict__ Wr)
{
    __shared__ float s_r1[HH][32], s_r2[HH][32];
    __shared__ int   s_kk[HH][32];
    __shared__ float Ux[32][68];     // [i][k] for current head chunk
    __shared__ float sB[64][68];     // [k][c] for current head chunk
    const int t  = threadIdx.x;
    const int b  = blockIdx.x;
    const int i0 = blockIdx.y * 32;

    if (t < 128) {
        const int h = t >> 5, ii = t & 31;
        const int idx = (b * HH + h) * NN + i0 + ii;
        s_r1[h][ii] = g_r1[idx];
        s_r2[h][ii] = g_r2[idx];
        s_kk[h][ii] = g_k[idx];
    }
    __syncthreads();

    const int ty = t >> 3;           // 0..31 -> owned i row
    const int tx = t & 7;            // c group of 8
    const int fq = t >> 4;           // formation: i half-group (0..15)
    const int fc = (t & 15) * 4;     // formation: float4 c offset
    const int sk = t >> 2;           // B staging: row k
    const int sq = t & 3;            // B staging: quarter

    ull acc[4];
    #pragma unroll
    for (int k = 0; k < 4; k++) acc[k] = 0ull;

    for (int h = 0; h < HH; h++) {
        // formation: coalesced float4 rows of S1f/P2f -> Ux
        {
            const size_t hb = ((size_t)(b * HH + h)) * 520 * 64;
            #pragma unroll
            for (int p = 0; p < 2; p++) {
                const int ii = fq + p * 16;
                const size_t base = hb + (size_t)s_kk[h][ii] * 64 + fc;
                float4 s = *(const float4*)(g_S1f + base);
                float4 q = *(const float4*)(g_P2f + base);
                const float r1v = s_r1[h][ii], r2v = s_r2[h][ii];
                float4 u;
                u.x = r1v * s.x + r2v * q.x;
                u.y = r1v * s.y + r2v * q.y;
                u.z = r1v * s.z + r2v * q.z;
                u.w = r1v * s.w + r2v * q.w;
                *(float4*)&Ux[ii][fc] = u;
            }
        }
        // stage B chunk = Wr[h][k][c]
        {
            const float4* wp = (const float4*)(Wr + h * 4096 + sk * 64 + sq * 16);
            #pragma unroll
            for (int j4 = 0; j4 < 4; j4++)
                *(float4*)&sB[sk][sq * 16 + j4 * 4] = wp[j4];
        }
        __syncthreads();

        // GEMM: acc[c8] += Ux[ty][k] * sB[k][c]
        #pragma unroll 8
        for (int k = 0; k < 64; k++) {
            float a = Ux[ty][k];
            ulonglong2 b0 = *(const ulonglong2*)&sB[k][tx * 8];
            ulonglong2 b1 = *(const ulonglong2*)&sB[k][tx * 8 + 4];
            ull ad = packdup(a);
            fma2(acc[0], ad, b0.x); fma2(acc[1], ad, b0.y);
            fma2(acc[2], ad, b1.x); fma2(acc[3], ad, b1.y);
        }
        __syncthreads();
    }

    // epilogue: bias + relu -> g_x
    {
        float v[8];
        #pragma unroll
        for (int c2 = 0; c2 < 4; c2++) {
            float2 f = unpack2(acc[c2]);
            v[c2 * 2 + 0] = fmaxf(f.x + cb[tx * 8 + c2 * 2 + 0], 0.f);
            v[c2 * 2 + 1] = fmaxf(f.y + cb[tx * 8 + c2 * 2 + 1], 0.f);
        }
        float* xp = g_x + (size_t)(b * NN + i0 + ty) * DD + tx * 8;
        *(float4*)xp       = make_float4(v[0], v[1], v[2], v[3]);
        *(float4*)(xp + 4) = make_float4(v[4], v[5], v[6], v[7]);
    }
}

// ---------------------------------------------------------------------------
// k_read: node-mean pooling + readout linear.
// ---------------------------------------------------------------------------
__global__ __launch_bounds__(256) void k_read(
    const float* __restrict__ rw, const float* __restrict__ rb,
    float* __restrict__ out)
{
    __shared__ float s_part[4][64];
    __shared__ float s_pool[64];
    const int t = threadIdx.x;
    const int b = blockIdx.x;
    const int c = t & 63, pg = t >> 6;
    float s = 0.f;
    for (int i = pg; i < NN; i += 4)
        s += g_x[(size_t)(b * NN + i) * DD + c];
    s_part[pg][c] = s;
    __syncthreads();
    if (t < 64)
        s_pool[t] = (s_part[0][t] + s_part[1][t] + s_part[2][t] + s_part[3][t])
                    * (1.0f / NN);
    __syncthreads();
    if (t < 64) {
        float a = rb[t];
        #pragma unroll 8
        for (int c2 = 0; c2 < 64; c2++)
            a += s_pool[c2] * rw[t * 64 + c2];
        out[b * 64 + t] = a;
    }
}

// ---------------------------------------------------------------------------
extern "C" void kernel_launch(void* const* d_in, const int* in_sizes, int n_in,
                              void* d_out, int out_size)
{
    const float* emb = (const float*)d_in[0];
    const float* lin = (const float*)d_in[1];
    const float* aS  = (const float*)d_in[2];
    const float* aD  = (const float*)d_in[3];
    const float* cb  = (const float*)d_in[4];
    const float* rw  = (const float*)d_in[5];
    const float* rb  = (const float*)d_in[6];
    float* out = (float*)d_out;

    float* gx = nullptr;
    cudaGetSymbolAddress((void**)&gx, g_x);
    float* gwr = nullptr;
    cudaGetSymbolAddress((void**)&gwr, g_Wr);
    float* gvsd = nullptr;
    cudaGetSymbolAddress((void**)&gvsd, g_vsd);

    const int PREP_SMEM = 12180 * 4;   // 48720 B
    cudaFuncSetAttribute(k_prep, cudaFuncAttributeMaxDynamicSharedMemorySize, PREP_SMEM);

    k_wr<<<12, 256>>>(lin, aS, aD);

    for (int l = 0; l < 3; l++) {
        const float* xin = (l == 0) ? emb : gx;
        k_att<<<dim3(64, 4), 512>>>(xin, gvsd + l * 2 * HH * 64);
        k_prep<<<dim3(64, 4), 512, PREP_SMEM>>>(xin);
        k_emit<<<dim3(64, 16), 256>>>(cb + l * CC, gwr + l * 16384);
    }
    k_read<<<64, 256>>>(rw, rb, out);
}

// round 12
// speedup vs baseline: 1.8952x; 1.8952x over previous
#include <cuda_runtime.h>
#include <cstdint>

#define BB 64
#define NN 512
#define DD 64
#define HH 4
#define CC 64
#define NEGS 0.2f

typedef unsigned long long ull;

// Scratch (device globals - no runtime allocation allowed)
__device__ float g_h[BB*HH*NN*CC];          // [b][h][n][c]  (head-major slabs)
__device__ float g_x[BB*NN*DD];             // layer activations
__device__ float g_asrc[BB*HH*NN];          // [b][h][n]
__device__ float g_adst[BB*HH*NN];          // [b][h][n]
__device__ float g_S1f[BB*HH*520*CC];       // full suffix sums (h-space)
__device__ float g_P2f[BB*HH*520*CC];       // full prefix sums (h-space)
__device__ float g_r1[BB*HH*NN];            // 0.25*e^{d}/den per i
__device__ float g_r2[BB*HH*NN];            // 0.25*e^{.2d}/den per i
__device__ int   g_k[BB*HH*NN];             // split index per i

// ---- f32x2 helpers -------------------------------------------------------
__device__ __forceinline__ void fma2(ull& d, ull a, ull b) {
    asm("fma.rn.f32x2 %0, %1, %2, %0;" : "+l"(d) : "l"(a), "l"(b));
}
__device__ __forceinline__ float2 unpack2(ull v) {
    float2 r; asm("mov.b64 {%0, %1}, %2;" : "=f"(r.x), "=f"(r.y) : "l"(v));
    return r;
}

// ---------------------------------------------------------------------------
// k_lin: h = x @ W^T, 64 rows x 64 cols per block (one head), 128 threads.
// A tile stored DUPLICATED in smem ([a,a] pairs) so f32x2 FMA needs no
// packdup MOVs: per k, 4x LDS.128 feed 16 FFMA2 (4i x 8c microtile).
// Epilogue: h -> g_h[b][h][n][c]; a_src/a_dst via 8-lane shfl reduce.
// dyn smem: s_x2[64][132] + s_w[64][72] = 52224 B
// ---------------------------------------------------------------------------
extern __shared__ float linsm[];

__global__ __launch_bounds__(128) void k_lin(
    const float* __restrict__ x, const float* __restrict__ W,
    const float* __restrict__ attS, const float* __restrict__ attD)
{
    float (*s_x2)[132] = (float(*)[132])linsm;             // [k][2*row] dup
    float (*s_w)[72]   = (float(*)[72])(linsm + 64 * 132); // [k][col]
    const int t    = threadIdx.x;
    const int row0 = blockIdx.x * 64;
    const int hh   = blockIdx.y;

    // stage: thread t covers row/col r = t&63, k-half kh = t>>6
    {
        const int r = t & 63, kh = t >> 6;
        const float4* xs = (const float4*)(x + (size_t)(row0 + r) * 64 + kh * 32);
        const float4* ws = (const float4*)(W + (size_t)(hh * 64 + r) * 64 + kh * 32);
        #pragma unroll
        for (int j4 = 0; j4 < 8; j4++) {
            float4 v = xs[j4];
            int k0 = kh * 32 + j4 * 4;
            *(float2*)&s_x2[k0+0][2*r] = make_float2(v.x, v.x);
            *(float2*)&s_x2[k0+1][2*r] = make_float2(v.y, v.y);
            *(float2*)&s_x2[k0+2][2*r] = make_float2(v.z, v.z);
            *(float2*)&s_x2[k0+3][2*r] = make_float2(v.w, v.w);
            float4 u = ws[j4];
            s_w[k0+0][r] = u.x;
            s_w[k0+1][r] = u.y;
            s_w[k0+2][r] = u.z;
            s_w[k0+3][r] = u.w;
        }
    }
    __syncthreads();

    const int tx = t & 7;    // c group (8 cols)
    const int ty = t >> 3;   // i group (4 rows), 0..15
    ull acc[16];
    #pragma unroll
    for (int k = 0; k < 16; k++) acc[k] = 0ull;

    #pragma unroll 4
    for (int k = 0; k < 64; k++) {
        ulonglong2 A0 = *(const ulonglong2*)&s_x2[k][ty * 8];      // (a0,a0),(a1,a1)
        ulonglong2 A1 = *(const ulonglong2*)&s_x2[k][ty * 8 + 4];  // (a2,a2),(a3,a3)
        ulonglong2 B0 = *(const ulonglong2*)&s_w[k][tx * 8];
        ulonglong2 B1 = *(const ulonglong2*)&s_w[k][tx * 8 + 4];
        ull ad[4] = {A0.x, A0.y, A1.x, A1.y};
        ull bp[4] = {B0.x, B0.y, B1.x, B1.y};
        #pragma unroll
        for (int i = 0; i < 4; i++) {
            fma2(acc[i * 4 + 0], ad[i], bp[0]);
            fma2(acc[i * 4 + 1], ad[i], bp[1]);
            fma2(acc[i * 4 + 2], ad[i], bp[2]);
            fma2(acc[i * 4 + 3], ad[i], bp[3]);
        }
    }

    // epilogue: h write ([b][h][n][c]) + a_src/a_dst
    float aSv[8], aDv[8];
    #pragma unroll
    for (int c = 0; c < 8; c++) {
        aSv[c] = attS[hh * 64 + tx * 8 + c];
        aDv[c] = attD[hh * 64 + tx * 8 + c];
    }
    #pragma unroll
    for (int i = 0; i < 4; i++) {
        float v[8];
        #pragma unroll
        for (int c2 = 0; c2 < 4; c2++) {
            float2 f = unpack2(acc[i * 4 + c2]);
            v[c2 * 2] = f.x; v[c2 * 2 + 1] = f.y;
        }
        int ng = row0 + ty * 4 + i;
        int b = ng >> 9, n = ng & 511;
        float* hp = g_h + ((size_t)(b * HH + hh) * NN + n) * CC + tx * 8;
        *(float4*)hp       = make_float4(v[0], v[1], v[2], v[3]);
        *(float4*)(hp + 4) = make_float4(v[4], v[5], v[6], v[7]);

        float ps = 0.f, pd = 0.f;
        #pragma unroll
        for (int c = 0; c < 8; c++) { ps += v[c] * aSv[c]; pd += v[c] * aDv[c]; }
        #pragma unroll
        for (int off = 4; off > 0; off >>= 1) {
            ps += __shfl_xor_sync(0xffffffffu, ps, off);
            pd += __shfl_xor_sync(0xffffffffu, pd, off);
        }
        if (tx == 0) {
            g_asrc[(b * HH + hh) * NN + n] = ps;
            g_adst[(b * HH + hh) * NN + n] = pd;
        }
    }
}

// ---------------------------------------------------------------------------
// k_prep, 512 threads, one block per (b,h): sort s; chunk(8) sums+scans over
// the contiguous g_h slab; full per-position suffix/prefix arrays to global;
// per-i scalars r1/r2/k. (Identical structure to the proven R10 prep.)
// ---------------------------------------------------------------------------
extern __shared__ float psm[];

__global__ __launch_bounds__(512) void k_prep()
{
    float* s_s  = psm;              // 512
    float* s_dd = psm + 512;
    float* s_W1 = psm + 1024;
    float* s_W2 = psm + 1536;
    int*   s_pj = (int*)(psm + 2048);
    float* CH1  = psm + 2560;       // [66][64]
    float* CH2  = psm + 6784;       // [66][64]
    float* CH1d = psm + 11008;      // [66]
    float* CH2d = psm + 11074;      // [66]
    float* s1d  = psm + 11140;      // [520]
    float* p2d  = psm + 11660;      // [520]  -> 12180 floats

    const int t = threadIdx.x;
    const int b = blockIdx.x;
    const int h = blockIdx.y;
    const int bh = b * HH + h;

    s_s[t]  = g_asrc[bh * NN + t];
    s_pj[t] = t;
    s_dd[t] = g_adst[bh * NN + t];

    // bitonic sort ascending; j<=32 stages warp-local
    {
        int prev_cross = 1;
        for (int k = 2; k <= 512; k <<= 1) {
            for (int j = k >> 1; j > 0; j >>= 1) {
                int cross = (j >= 64);
                if (cross | prev_cross) __syncthreads(); else __syncwarp();
                if (t < 256) {
                    int i = ((t & ~(j - 1)) << 1) | (t & (j - 1));
                    int p = i | j;
                    bool up = ((i & k) == 0);
                    float ki = s_s[i], kp = s_s[p];
                    if (up ? (ki > kp) : (ki < kp)) {
                        s_s[i] = kp; s_s[p] = ki;
                        int tmp = s_pj[i]; s_pj[i] = s_pj[p]; s_pj[p] = tmp;
                    }
                }
                prev_cross = cross;
            }
        }
        __syncthreads();
    }

    // sorted weights + per-i split
    int k_reg;
    {
        float sv = s_s[t];
        s_W1[t] = __expf(sv);
        s_W2[t] = __expf(NEGS * sv);
        float thr = -s_dd[t];
        int lo = 0, hi = 512;
        while (lo < hi) {
            int mid = (lo + hi) >> 1;
            if (s_s[mid] < thr) lo = mid + 1; else hi = mid;
        }
        k_reg = lo;
    }
    __syncthreads();

    const float* hb = g_h + (size_t)bh * NN * CC;

    // chunk sums (float2 over h rows)
    #pragma unroll
    for (int p = t; p < 2048; p += 512) {
        int m = p >> 5, c = (p & 31) * 2;
        float2 f1 = make_float2(0.f, 0.f), f2 = make_float2(0.f, 0.f);
        #pragma unroll
        for (int r = 0; r < 8; r++) {
            int jj = m * 8 + r;
            float2 hv = *(const float2*)(hb + (size_t)s_pj[jj] * 64 + c);
            float w1 = s_W1[jj], w2 = s_W2[jj];
            f1.x += w1 * hv.x; f1.y += w1 * hv.y;
            f2.x += w2 * hv.x; f2.y += w2 * hv.y;
        }
        *(float2*)&CH1[m * 64 + c] = f1;
        *(float2*)&CH2[(m + 1) * 64 + c] = f2;
    }
    if (t < 64) {
        int m = t;
        float f1 = 0.f, f2 = 0.f;
        #pragma unroll
        for (int r = 0; r < 8; r++) { f1 += s_W1[m*8+r]; f2 += s_W2[m*8+r]; }
        CH1d[m] = f1;
        CH2d[m + 1] = f2;
    }
    __syncthreads();

    // chunk scans
    if (t < 64) {
        const int c = t;
        CH1[64 * 64 + c] = 0.f;
        CH2[c] = 0.f;
        float run = 0.f;
        for (int m = 63; m >= 0; m--) { run += CH1[m * 64 + c]; CH1[m * 64 + c] = run; }
        float run2 = 0.f;
        for (int m = 1; m <= 64; m++) { run2 += CH2[m * 64 + c]; CH2[m * 64 + c] = run2; }
    } else if (t == 64) {
        CH1d[64] = 0.f;
        float run = 0.f;
        for (int m = 63; m >= 0; m--) { run += CH1d[m]; CH1d[m] = run; }
    } else if (t == 65) {
        CH2d[0] = 0.f;
        float run = 0.f;
        for (int m = 1; m <= 64; m++) { run += CH2d[m]; CH2d[m] = run; }
    }
    __syncthreads();

    // full per-position arrays + scalar arrays
    {
        float* S1 = g_S1f + (size_t)bh * 520 * 64;
        float* P2 = g_P2f + (size_t)bh * 520 * 64;
        #pragma unroll
        for (int p = t; p < 2048; p += 512) {
            int m = p >> 5, c = (p & 31) * 2;
            float2 hv[8];
            #pragma unroll
            for (int r = 0; r < 8; r++)
                hv[r] = *(const float2*)(hb + (size_t)s_pj[m * 8 + r] * 64 + c);
            float2 run1 = *(const float2*)&CH1[(m + 1) * 64 + c];
            #pragma unroll
            for (int r = 7; r >= 0; r--) {
                float w = s_W1[m * 8 + r];
                run1.x += w * hv[r].x; run1.y += w * hv[r].y;
                *(float2*)&S1[(size_t)(m * 8 + r) * 64 + c] = run1;
            }
            float2 run2 = *(const float2*)&CH2[m * 64 + c];
            #pragma unroll
            for (int r = 0; r < 8; r++) {
                *(float2*)&P2[(size_t)(m * 8 + r) * 64 + c] = run2;
                float w = s_W2[m * 8 + r];
                run2.x += w * hv[r].x; run2.y += w * hv[r].y;
            }
        }
        if (t < 64) {
            int m = t;
            float run1 = CH1d[m + 1];
            #pragma unroll
            for (int r = 7; r >= 0; r--) { run1 += s_W1[m*8+r]; s1d[m*8+r] = run1; }
            float run2 = CH2d[m];
            #pragma unroll
            for (int r = 0; r < 8; r++) { p2d[m*8+r] = run2; run2 += s_W2[m*8+r]; }
        }
        if (t < 64) {
            S1[(size_t)512 * 64 + t] = 0.f;
            P2[(size_t)512 * 64 + t] = CH2[64 * 64 + t];
        }
        if (t == 64) { s1d[512] = 0.f; p2d[512] = CH2d[64]; }
    }
    __syncthreads();

    // per-i scalars
    {
        float dv = s_dd[t];
        float e1 = __expf(dv);
        float e2 = __expf(NEGS * dv);
        float den = e1 * s1d[k_reg] + e2 * p2d[k_reg];
        float inv = 0.25f * __frcp_rn(den);
        int gi = bh * NN + t;
        g_r1[gi] = e1 * inv;
        g_r2[gi] = e2 * inv;
        g_k[gi]  = k_reg;
    }
}

// ---------------------------------------------------------------------------
// k_emit (simple, proven-fast): x[b,i,c] =
//   relu( sum_h (r1*S1f[k_i][c] + r2*P2f[k_i][c]) + bias[c] )
// 2 coalesced loads + 2 FMA per (i,c,h); head combine fused.
// ---------------------------------------------------------------------------
__global__ __launch_bounds__(256) void k_emit(const float* __restrict__ cb)
{
    __shared__ float s_r1[4][64], s_r2[4][64];
    __shared__ int   s_kk[4][64];
    const int t  = threadIdx.x;
    const int b  = blockIdx.x;
    const int i0 = blockIdx.y * 64;

    {
        const int h = t >> 6, ii = t & 63;
        const int idx = (b * HH + h) * NN + i0 + ii;
        s_r1[h][ii] = g_r1[idx];
        s_r2[h][ii] = g_r2[idx];
        s_kk[h][ii] = g_k[idx];
    }
    __syncthreads();

    const int c  = t & 63;
    const int ig = t >> 6;
    const float bias = cb[c];
    const size_t hb0 = (size_t)(b * HH) * 520 * 64;

    for (int ii = ig; ii < 64; ii += 4) {
        float acc = bias;
        #pragma unroll
        for (int h = 0; h < HH; h++) {
            const size_t base = hb0 + ((size_t)h * 520 + s_kk[h][ii]) * 64 + c;
            acc += s_r1[h][ii] * g_S1f[base] + s_r2[h][ii] * g_P2f[base];
        }
        g_x[(size_t)(b * NN + i0 + ii) * DD + c] = fmaxf(acc, 0.f);
    }
}

// ---------------------------------------------------------------------------
// k_read: node-mean pooling + readout linear.
// ---------------------------------------------------------------------------
__global__ __launch_bounds__(256) void k_read(
    const float* __restrict__ rw, const float* __restrict__ rb,
    float* __restrict__ out)
{
    __shared__ float s_part[4][64];
    __shared__ float s_pool[64];
    const int t = threadIdx.x;
    const int b = blockIdx.x;
    const int c = t & 63, pg = t >> 6;
    float s = 0.f;
    for (int i = pg; i < NN; i += 4)
        s += g_x[(size_t)(b * NN + i) * DD + c];
    s_part[pg][c] = s;
    __syncthreads();
    if (t < 64)
        s_pool[t] = (s_part[0][t] + s_part[1][t] + s_part[2][t] + s_part[3][t])
                    * (1.0f / NN);
    __syncthreads();
    if (t < 64) {
        float a = rb[t];
        #pragma unroll 8
        for (int c2 = 0; c2 < 64; c2++)
            a += s_pool[c2] * rw[t * 64 + c2];
        out[b * 64 + t] = a;
    }
}

// ---------------------------------------------------------------------------
extern "C" void kernel_launch(void* const* d_in, const int* in_sizes, int n_in,
                              void* d_out, int out_size)
{
    const float* emb = (const float*)d_in[0];
    const float* lin = (const float*)d_in[1];
    const float* aS  = (const float*)d_in[2];
    const float* aD  = (const float*)d_in[3];
    const float* cb  = (const float*)d_in[4];
    const float* rw  = (const float*)d_in[5];
    const float* rb  = (const float*)d_in[6];
    float* out = (float*)d_out;

    float* gx = nullptr;
    cudaGetSymbolAddress((void**)&gx, g_x);

    const int LIN_SMEM  = (64 * 132 + 64 * 72) * 4;  // 52224 B
    const int PREP_SMEM = 12180 * 4;                 // 48720 B
    cudaFuncSetAttribute(k_lin, cudaFuncAttributeMaxDynamicSharedMemorySize, LIN_SMEM);
    cudaFuncSetAttribute(k_prep, cudaFuncAttributeMaxDynamicSharedMemorySize, PREP_SMEM);

    for (int l = 0; l < 3; l++) {
        const float* xin = (l == 0) ? emb : gx;
        k_lin<<<dim3(512, 4), 128, LIN_SMEM>>>(xin, lin + l * 16384,
                                               aS + l * HH * CC, aD + l * HH * CC);
        k_prep<<<dim3(64, 4), 512, PREP_SMEM>>>();
        k_emit<<<dim3(64, 8), 256>>>(cb + l * CC);
    }
    k_read<<<64, 256>>>(rw, rb, out);
}

// round 13
// speedup vs baseline: 2.5986x; 1.3711x over previous
#include <cuda_runtime.h>
#include <cstdint>

#define BB 64
#define NN 512
#define DD 64
#define HH 4
#define CC 64
#define NEGS 0.2f

// Scratch (device globals - no runtime allocation allowed)
__device__ float g_h[BB*HH*NN*CC];          // [b][h][n][c]  (head-major slabs)
__device__ float g_x[BB*NN*DD];             // layer activations
__device__ float g_asrc[BB*HH*NN];          // [b][h][n]
__device__ float g_adst[BB*HH*NN];          // [b][h][n]
__device__ float g_S1f[BB*HH*520*CC];       // full suffix sums (h-space)
__device__ float g_P2f[BB*HH*520*CC];       // full prefix sums (h-space)
__device__ float g_r1[BB*HH*NN];            // 0.25*e^{d}/den per i
__device__ float g_r2[BB*HH*NN];            // 0.25*e^{.2d}/den per i
__device__ int   g_k[BB*HH*NN];             // split index per i

// ---------------------------------------------------------------------------
// k_lin (R7-proven scalar): h = x @ W^T, 64x64 tile, one head per blockIdx.y,
// 256 threads, 4i x 4c microtile. Epilogue: h -> g_h[b][h][n][c] slab +
// a_src/a_dst via shfl reduce.
// ---------------------------------------------------------------------------
__global__ __launch_bounds__(256) void k_lin(
    const float* __restrict__ x, const float* __restrict__ W,
    const float* __restrict__ attS, const float* __restrict__ attD)
{
    __shared__ float s_x[64][68];   // transposed [k][row]
    __shared__ float s_w[64][68];   // transposed [k][col]
    const int t    = threadIdx.x;
    const int row0 = blockIdx.x * 64;
    const int hh   = blockIdx.y;

    {
        const int li = t >> 2;
        const int c4 = t & 3;
        const float4* x4 = (const float4*)x;
        const float4* w4 = (const float4*)W;
        #pragma unroll
        for (int q = 0; q < 4; q++) {
            int kc = c4 + q * 4;
            float4 v = x4[(row0 + li) * 16 + kc];
            s_x[kc*4+0][li] = v.x; s_x[kc*4+1][li] = v.y;
            s_x[kc*4+2][li] = v.z; s_x[kc*4+3][li] = v.w;
            float4 u = w4[(hh * 64 + li) * 16 + kc];
            s_w[kc*4+0][li] = u.x; s_w[kc*4+1][li] = u.y;
            s_w[kc*4+2][li] = u.z; s_w[kc*4+3][li] = u.w;
        }
    }
    __syncthreads();

    const int tx = t & 15, ty = t >> 4;
    float acc[4][4] = {};
    #pragma unroll
    for (int k = 0; k < 64; k++) {
        float4 a = *(const float4*)&s_x[k][ty * 4];
        float4 b = *(const float4*)&s_w[k][tx * 4];
        float av[4] = {a.x, a.y, a.z, a.w};
        float bv[4] = {b.x, b.y, b.z, b.w};
        #pragma unroll
        for (int i = 0; i < 4; i++)
            #pragma unroll
            for (int c = 0; c < 4; c++)
                acc[i][c] += av[i] * bv[c];
    }

    // h write into [b][h][n][c] slab
    #pragma unroll
    for (int i = 0; i < 4; i++) {
        int ng = row0 + ty * 4 + i;
        int b = ng >> 9, n = ng & 511;
        *(float4*)&g_h[((size_t)(b * HH + hh) * NN + n) * CC + tx * 4] =
            make_float4(acc[i][0], acc[i][1], acc[i][2], acc[i][3]);
    }

    float aSv[4], aDv[4];
    #pragma unroll
    for (int c = 0; c < 4; c++) {
        aSv[c] = attS[hh * 64 + tx * 4 + c];
        aDv[c] = attD[hh * 64 + tx * 4 + c];
    }
    #pragma unroll
    for (int i = 0; i < 4; i++) {
        float ps = 0.f, pd = 0.f;
        #pragma unroll
        for (int c = 0; c < 4; c++) { ps += acc[i][c] * aSv[c]; pd += acc[i][c] * aDv[c]; }
        #pragma unroll
        for (int off = 8; off > 0; off >>= 1) {
            ps += __shfl_xor_sync(0xffffffffu, ps, off);
            pd += __shfl_xor_sync(0xffffffffu, pd, off);
        }
        if (tx == 0) {
            int ng = row0 + ty * 4 + i;
            int b = ng >> 9, n = ng & 511;
            g_asrc[(b * HH + hh) * NN + n] = ps;
            g_adst[(b * HH + hh) * NN + n] = pd;
        }
    }
}

// ---------------------------------------------------------------------------
// k_prep (R12-proven), 512 threads, one block per (b,h): sort s; chunk(8)
// sums+scans over the contiguous g_h slab; full per-position suffix/prefix
// arrays to global; per-i scalars r1/r2/k.
// ---------------------------------------------------------------------------
extern __shared__ float psm[];

__global__ __launch_bounds__(512) void k_prep()
{
    float* s_s  = psm;              // 512
    float* s_dd = psm + 512;
    float* s_W1 = psm + 1024;
    float* s_W2 = psm + 1536;
    int*   s_pj = (int*)(psm + 2048);
    float* CH1  = psm + 2560;       // [66][64]
    float* CH2  = psm + 6784;       // [66][64]
    float* CH1d = psm + 11008;      // [66]
    float* CH2d = psm + 11074;      // [66]
    float* s1d  = psm + 11140;      // [520]
    float* p2d  = psm + 11660;      // [520]  -> 12180 floats

    const int t = threadIdx.x;
    const int b = blockIdx.x;
    const int h = blockIdx.y;
    const int bh = b * HH + h;

    s_s[t]  = g_asrc[bh * NN + t];
    s_pj[t] = t;
    s_dd[t] = g_adst[bh * NN + t];

    // bitonic sort ascending; j<=32 stages warp-local
    {
        int prev_cross = 1;
        for (int k = 2; k <= 512; k <<= 1) {
            for (int j = k >> 1; j > 0; j >>= 1) {
                int cross = (j >= 64);
                if (cross | prev_cross) __syncthreads(); else __syncwarp();
                if (t < 256) {
                    int i = ((t & ~(j - 1)) << 1) | (t & (j - 1));
                    int p = i | j;
                    bool up = ((i & k) == 0);
                    float ki = s_s[i], kp = s_s[p];
                    if (up ? (ki > kp) : (ki < kp)) {
                        s_s[i] = kp; s_s[p] = ki;
                        int tmp = s_pj[i]; s_pj[i] = s_pj[p]; s_pj[p] = tmp;
                    }
                }
                prev_cross = cross;
            }
        }
        __syncthreads();
    }

    // sorted weights + per-i split
    int k_reg;
    {
        float sv = s_s[t];
        s_W1[t] = __expf(sv);
        s_W2[t] = __expf(NEGS * sv);
        float thr = -s_dd[t];
        int lo = 0, hi = 512;
        while (lo < hi) {
            int mid = (lo + hi) >> 1;
            if (s_s[mid] < thr) lo = mid + 1; else hi = mid;
        }
        k_reg = lo;
    }
    __syncthreads();

    const float* hb = g_h + (size_t)bh * NN * CC;

    // chunk sums (float2 over h rows)
    #pragma unroll
    for (int p = t; p < 2048; p += 512) {
        int m = p >> 5, c = (p & 31) * 2;
        float2 f1 = make_float2(0.f, 0.f), f2 = make_float2(0.f, 0.f);
        #pragma unroll
        for (int r = 0; r < 8; r++) {
            int jj = m * 8 + r;
            float2 hv = *(const float2*)(hb + (size_t)s_pj[jj] * 64 + c);
            float w1 = s_W1[jj], w2 = s_W2[jj];
            f1.x += w1 * hv.x; f1.y += w1 * hv.y;
            f2.x += w2 * hv.x; f2.y += w2 * hv.y;
        }
        *(float2*)&CH1[m * 64 + c] = f1;
        *(float2*)&CH2[(m + 1) * 64 + c] = f2;
    }
    if (t < 64) {
        int m = t;
        float f1 = 0.f, f2 = 0.f;
        #pragma unroll
        for (int r = 0; r < 8; r++) { f1 += s_W1[m*8+r]; f2 += s_W2[m*8+r]; }
        CH1d[m] = f1;
        CH2d[m + 1] = f2;
    }
    __syncthreads();

    // chunk scans
    if (t < 64) {
        const int c = t;
        CH1[64 * 64 + c] = 0.f;
        CH2[c] = 0.f;
        float run = 0.f;
        for (int m = 63; m >= 0; m--) { run += CH1[m * 64 + c]; CH1[m * 64 + c] = run; }
        float run2 = 0.f;
        for (int m = 1; m <= 64; m++) { run2 += CH2[m * 64 + c]; CH2[m * 64 + c] = run2; }
    } else if (t == 64) {
        CH1d[64] = 0.f;
        float run = 0.f;
        for (int m = 63; m >= 0; m--) { run += CH1d[m]; CH1d[m] = run; }
    } else if (t == 65) {
        CH2d[0] = 0.f;
        float run = 0.f;
        for (int m = 1; m <= 64; m++) { run += CH2d[m]; CH2d[m] = run; }
    }
    __syncthreads();

    // full per-position arrays + scalar arrays
    {
        float* S1 = g_S1f + (size_t)bh * 520 * 64;
        float* P2 = g_P2f + (size_t)bh * 520 * 64;
        #pragma unroll
        for (int p = t; p < 2048; p += 512) {
            int m = p >> 5, c = (p & 31) * 2;
            float2 hv[8];
            #pragma unroll
            for (int r = 0; r < 8; r++)
                hv[r] = *(const float2*)(hb + (size_t)s_pj[m * 8 + r] * 64 + c);
            float2 run1 = *(const float2*)&CH1[(m + 1) * 64 + c];
            #pragma unroll
            for (int r = 7; r >= 0; r--) {
                float w = s_W1[m * 8 + r];
                run1.x += w * hv[r].x; run1.y += w * hv[r].y;
                *(float2*)&S1[(size_t)(m * 8 + r) * 64 + c] = run1;
            }
            float2 run2 = *(const float2*)&CH2[m * 64 + c];
            #pragma unroll
            for (int r = 0; r < 8; r++) {
                *(float2*)&P2[(size_t)(m * 8 + r) * 64 + c] = run2;
                float w = s_W2[m * 8 + r];
                run2.x += w * hv[r].x; run2.y += w * hv[r].y;
            }
        }
        if (t < 64) {
            int m = t;
            float run1 = CH1d[m + 1];
            #pragma unroll
            for (int r = 7; r >= 0; r--) { run1 += s_W1[m*8+r]; s1d[m*8+r] = run1; }
            float run2 = CH2d[m];
            #pragma unroll
            for (int r = 0; r < 8; r++) { p2d[m*8+r] = run2; run2 += s_W2[m*8+r]; }
        }
        if (t < 64) {
            S1[(size_t)512 * 64 + t] = 0.f;
            P2[(size_t)512 * 64 + t] = CH2[64 * 64 + t];
        }
        if (t == 64) { s1d[512] = 0.f; p2d[512] = CH2d[64]; }
    }
    __syncthreads();

    // per-i scalars
    {
        float dv = s_dd[t];
        float e1 = __expf(dv);
        float e2 = __expf(NEGS * dv);
        float den = e1 * s1d[k_reg] + e2 * p2d[k_reg];
        float inv = 0.25f * __frcp_rn(den);
        int gi = bh * NN + t;
        g_r1[gi] = e1 * inv;
        g_r2[gi] = e2 * inv;
        g_k[gi]  = k_reg;
    }
}

// ---------------------------------------------------------------------------
// k_emit (R8/R12-proven): x[b,i,c] =
//   relu( sum_h (r1*S1f[k_i][c] + r2*P2f[k_i][c]) + bias[c] )
// ---------------------------------------------------------------------------
__global__ __launch_bounds__(256) void k_emit(const float* __restrict__ cb)
{
    __shared__ float s_r1[4][64], s_r2[4][64];
    __shared__ int   s_kk[4][64];
    const int t  = threadIdx.x;
    const int b  = blockIdx.x;
    const int i0 = blockIdx.y * 64;

    {
        const int h = t >> 6, ii = t & 63;
        const int idx = (b * HH + h) * NN + i0 + ii;
        s_r1[h][ii] = g_r1[idx];
        s_r2[h][ii] = g_r2[idx];
        s_kk[h][ii] = g_k[idx];
    }
    __syncthreads();

    const int c  = t & 63;
    const int ig = t >> 6;
    const float bias = cb[c];
    const size_t hb0 = (size_t)(b * HH) * 520 * 64;

    for (int ii = ig; ii < 64; ii += 4) {
        float acc = bias;
        #pragma unroll
        for (int h = 0; h < HH; h++) {
            const size_t base = hb0 + ((size_t)h * 520 + s_kk[h][ii]) * 64 + c;
            acc += s_r1[h][ii] * g_S1f[base] + s_r2[h][ii] * g_P2f[base];
        }
        g_x[(size_t)(b * NN + i0 + ii) * DD + c] = fmaxf(acc, 0.f);
    }
}

// ---------------------------------------------------------------------------
// k_read: node-mean pooling + readout linear.
// ---------------------------------------------------------------------------
__global__ __launch_bounds__(256) void k_read(
    const float* __restrict__ rw, const float* __restrict__ rb,
    float* __restrict__ out)
{
    __shared__ float s_part[4][64];
    __shared__ float s_pool[64];
    const int t = threadIdx.x;
    const int b = blockIdx.x;
    const int c = t & 63, pg = t >> 6;
    float s = 0.f;
    for (int i = pg; i < NN; i += 4)
        s += g_x[(size_t)(b * NN + i) * DD + c];
    s_part[pg][c] = s;
    __syncthreads();
    if (t < 64)
        s_pool[t] = (s_part[0][t] + s_part[1][t] + s_part[2][t] + s_part[3][t])
                    * (1.0f / NN);
    __syncthreads();
    if (t < 64) {
        float a = rb[t];
        #pragma unroll 8
        for (int c2 = 0; c2 < 64; c2++)
            a += s_pool[c2] * rw[t * 64 + c2];
        out[b * 64 + t] = a;
    }
}

// ---------------------------------------------------------------------------
extern "C" void kernel_launch(void* const* d_in, const int* in_sizes, int n_in,
                              void* d_out, int out_size)
{
    const float* emb = (const float*)d_in[0];
    const float* lin = (const float*)d_in[1];
    const float* aS  = (const float*)d_in[2];
    const float* aD  = (const float*)d_in[3];
    const float* cb  = (const float*)d_in[4];
    const float* rw  = (const float*)d_in[5];
    const float* rb  = (const float*)d_in[6];
    float* out = (float*)d_out;

    float* gx = nullptr;
    cudaGetSymbolAddress((void**)&gx, g_x);

    const int PREP_SMEM = 12180 * 4;   // 48720 B
    cudaFuncSetAttribute(k_prep, cudaFuncAttributeMaxDynamicSharedMemorySize, PREP_SMEM);

    for (int l = 0; l < 3; l++) {
        const float* xin = (l == 0) ? emb : gx;
        k_lin<<<dim3(512, 4), 256>>>(xin, lin + l * 16384,
                                     aS + l * HH * CC, aD + l * HH * CC);
        k_prep<<<dim3(64, 4), 512, PREP_SMEM>>>();
        k_emit<<<dim3(64, 8), 256>>>(cb + l * CC);
    }
    k_read<<<64, 256>>>(rw, rb, out);
}